// round 10
// baseline (speedup 1.0000x reference)
#include <cuda_runtime.h>
#include <cuda_fp16.h>
#include <stdint.h>

#define WIMG 2048
#define HIMG 64
#define CINC 64
#define COUTC 64
#define TILE 256
#define NTHREADS 256
#define HW (HIMG*WIMG)

__device__ double g_sum[COUTC];
__device__ double g_sumsq[COUTC];
__device__ float  g_scale[COUTC];
__device__ float  g_bias[COUTC];
// A operand in mma.m16n8k16 fragment order: [slice][ks][mt][hi/lo][lane][4xu32], x64-scaled fp16
__device__ __align__(16) unsigned char g_wfrag[9 * 4 * 4 * 2 * 512];

#define SO_WSP    0
#define SO_BSP    1024
#define SO_WCH    1280
#define SO_BCH    2304
#define SO_PSUM   2560     /* 8 warps x 64 floats */
#define SO_PSQ    4608
#define SO_XROW   6656     /* 32 pairs x 260 half2 = 33280 */
#define SO_WCOEF  40960    /* 64*256*4 = 65536 */
#define SO_V      106496   /* 2 x 32768 (double-buffered fp16 V panel) */
#define SMEM_TOT  (172032 + 1024)

#define SW128(o) ((o) ^ (((o) >> 3) & 0x70))

__device__ __forceinline__ uint32_t smem_u32(const void* p) {
    uint32_t a;
    asm("{ .reg .u64 t; cvta.to.shared.u64 t, %1; cvt.u32.u64 %0, t; }" : "=r"(a) : "l"(p));
    return a;
}
__device__ __forceinline__ void ldsm_x2(uint32_t a, uint32_t* r) {
    asm volatile("ldmatrix.sync.aligned.m8n8.x2.shared.b16 {%0,%1}, [%2];"
                 : "=r"(r[0]), "=r"(r[1]) : "r"(a));
}
__device__ __forceinline__ void mma16816(float* c, const uint32_t* a, const uint32_t* b) {
    asm volatile("mma.sync.aligned.m16n8k16.row.col.f32.f16.f16.f32 "
                 "{%0,%1,%2,%3}, {%4,%5,%6,%7}, {%8,%9}, {%0,%1,%2,%3};"
                 : "+f"(c[0]), "+f"(c[1]), "+f"(c[2]), "+f"(c[3])
                 : "r"(a[0]), "r"(a[1]), "r"(a[2]), "r"(a[3]), "r"(b[0]), "r"(b[1]));
}

__global__ void zero_kernel() {
    int t = threadIdx.x;
    if (t < COUTC) { g_sum[t] = 0.0; g_sumsq[t] = 0.0; }
}

// write 64*w_agg as fp16 hi/lo in mma fragment layout
__global__ void wagg_prep(const float* __restrict__ w_agg) {
    int t = blockIdx.x * blockDim.x + threadIdx.x;
    if (t >= 9 * 4 * 4 * 32) return;
    int slice = t >> 9;
    int ks = (t >> 7) & 3;
    int mt = (t >> 5) & 3;
    int lane = t & 31;
    uint32_t hi[4], lo[4];
#pragma unroll
    for (int q = 0; q < 4; q++) {
        int row = mt * 16 + (lane >> 2) + (q & 1) * 8;
        int kc = ks * 16 + (lane & 3) * 2 + (q >> 1) * 8;
        float w0 = w_agg[row * 576 + slice * 64 + kc] * 64.0f;
        float w1 = w_agg[row * 576 + slice * 64 + kc + 1] * 64.0f;
        __half h0 = __float2half_rn(w0);
        __half h1 = __float2half_rn(w1);
        __half l0 = __float2half_rn(w0 - __half2float(h0));
        __half l1 = __float2half_rn(w1 - __half2float(h1));
        hi[q] = (uint32_t)__half_as_ushort(h0) | ((uint32_t)__half_as_ushort(h1) << 16);
        lo[q] = (uint32_t)__half_as_ushort(l0) | ((uint32_t)__half_as_ushort(l1) << 16);
    }
    int base = (slice * 16 + ks * 4 + mt) * 2;
    *(uint4*)(g_wfrag + (base + 0) * 512 + lane * 16) = *(uint4*)hi;
    *(uint4*)(g_wfrag + (base + 1) * 512 + lane * 16) = *(uint4*)lo;
}

__global__ void __launch_bounds__(NTHREADS, 1)
main_kernel(const float* __restrict__ x, const int* __restrict__ mask,
            const float* __restrict__ w_spatial, const float* __restrict__ b_spatial,
            const float* __restrict__ w_channel, const float* __restrict__ b_channel,
            float* __restrict__ out) {
    extern __shared__ unsigned char smraw[];
    const uint32_t raw = smem_u32(smraw);
    const uint32_t sb = (raw + 1023u) & ~1023u;
    unsigned char* smb = smraw + (sb - raw);

    float* wsp   = (float*)(smb + SO_WSP);
    float* bsp   = (float*)(smb + SO_BSP);
    float* wch   = (float*)(smb + SO_WCH);
    float* bch   = (float*)(smb + SO_BCH);
    float* psum  = (float*)(smb + SO_PSUM);
    float* psq   = (float*)(smb + SO_PSQ);
    float* wcoef = (float*)(smb + SO_WCOEF);

    const int tid = threadIdx.x;
    const int wid = tid >> 5;
    const int lid = tid & 31;
    const int col0 = blockIdx.x * TILE;
    const int y = blockIdx.y;
    const int b = blockIdx.z;

    for (int i = tid; i < CINC * 4; i += NTHREADS) { wsp[i] = w_spatial[i]; wch[i] = w_channel[i]; }
    for (int i = tid; i < CINC; i += NTHREADS) { bsp[i] = b_spatial[i]; bch[i] = b_channel[i]; }

    // ---------- phase A: dual-softmax prep (1 thread = 1 pixel) ----------
    const int col = col0 + tid;
    float d0[9], d1[9], d2[9], d3[9], mv[9];
    {
        int cbase = ((b * 67) * HIMG + y) * WIMG + col;
        float cc0 = x[cbase];
        float cc1 = x[cbase + HW];
        float cc2 = x[cbase + 2 * HW];
        float rc = sqrtf(cc0 * cc0 + cc1 * cc1 + cc2 * cc2);
#pragma unroll
        for (int k = 0; k < 9; k++) {
            int yy = y + k / 3 - 1;
            int xx = col + k % 3 - 1;
            bool v = (yy >= 0 && yy < HIMG && xx >= 0 && xx < WIMG);
            float p0 = 0.f, p1 = 0.f, p2 = 0.f, m = 0.f;
            if (v) {
                int base = ((b * 67) * HIMG + yy) * WIMG + xx;
                p0 = x[base]; p1 = x[base + HW]; p2 = x[base + 2 * HW];
                m = (float)mask[(b * HIMG + yy) * WIMG + xx];
            }
            float r = sqrtf(p0 * p0 + p1 * p1 + p2 * p2);
            d0[k] = p0 - cc0; d1[k] = p1 - cc1; d2[k] = p2 - cc2; d3[k] = r - rc;
            mv[k] = m;
        }
    }
    __syncthreads();   // weight copies visible

    float smax[9];
#pragma unroll
    for (int k = 0; k < 9; k++) smax[k] = -3.0e38f;
    float cmax = -3.0e38f;
    for (int c = 0; c < CINC; c++) {
        float ws0 = wsp[c*4], ws1 = wsp[c*4+1], ws2 = wsp[c*4+2], ws3 = wsp[c*4+3];
        float wc0 = wch[c*4], wc1 = wch[c*4+1], wc2 = wch[c*4+2], wc3 = wch[c*4+3];
        float bs = bsp[c], bc = bch[c];
        float tmax = -3.0e38f;
#pragma unroll
        for (int k = 0; k < 9; k++) {
            float sv = fmaf(d3[k], ws3, fmaf(d2[k], ws2, fmaf(d1[k], ws1, fmaf(d0[k], ws0, bs))));
            smax[k] = fmaxf(smax[k], sv);
            float tv = fmaf(d3[k], wc3, fmaf(d2[k], wc2, fmaf(d1[k], wc1, fmaf(d0[k], wc0, bc))));
            tmax = fmaxf(tmax, tv);
        }
        wcoef[c * 256 + tid] = tmax;   // thread-private column
        cmax = fmaxf(cmax, tmax);
    }
    float csum = 0.f;
    for (int c = 0; c < CINC; c++) {
        float e = __expf(wcoef[c * 256 + tid] - cmax);
        wcoef[c * 256 + tid] = e;
        csum += e;
    }
    float cinv = 1.f / csum;
    float wmx = smax[0];
#pragma unroll
    for (int k = 1; k < 9; k++) wmx = fmaxf(wmx, smax[k]);
    float es[9], ssum = 0.f;
#pragma unroll
    for (int k = 0; k < 9; k++) { es[k] = __expf(smax[k] - wmx); ssum += es[k]; }
    float sinv = 1.f / ssum;
    float aw[9], am[9];
#pragma unroll
    for (int k = 0; k < 9; k++) { aw[k] = mv[k] * es[k] * sinv; am[k] = mv[k] * cinv; }

    // ---------- phase B: fp16 2-product MMA, warp-desynchronized ----------
    const int wbase = wid * 32;
    uint32_t bswz[4];
    {
        uint32_t blocal = (uint32_t)((lid & 7) * 128 + ((lid >> 3) & 1) * 16);
#pragma unroll
        for (int ks = 0; ks < 4; ks++) bswz[ks] = SW128(blocal + ks * 32);
    }
    const uint4* WF = (const uint4*)g_wfrag;

    float acc[4][4][4];
#pragma unroll
    for (int mt = 0; mt < 4; mt++)
#pragma unroll
        for (int nt = 0; nt < 4; nt++)
#pragma unroll
            for (int q = 0; q < 4; q++) acc[mt][nt][q] = 0.f;

    int slice = 0;
    for (int i3 = 0; i3 < 3; i3++) {
        int yy = y + i3 - 1;
        __syncthreads();   // all readers of previous xrow done
        if (yy >= 0 && yy < HIMG) {
            int rbase = ((b * 67 + 3) * HIMG + yy) * WIMG;
            int gcol = col0 - 1 + tid;
            bool gv = (gcol >= 0 && gcol < WIMG);
#pragma unroll 4
            for (int p = 0; p < 32; p++) {
                float x0 = gv ? x[rbase + (2 * p) * HW + gcol] : 0.f;
                float x1 = gv ? x[rbase + (2 * p + 1) * HW + gcol] : 0.f;
                uint32_t x2;
                asm("cvt.rn.f16x2.f32 %0, %1, %2;" : "=r"(x2) : "f"(x1), "f"(x0));
                *(uint32_t*)(smb + SO_XROW + (p * 260 + tid) * 4) = x2;
            }
            if (tid < 2) {
                int g2 = col0 + 255 + tid;
                bool v2 = (g2 < WIMG);
                for (int p = 0; p < 32; p++) {
                    float x0 = v2 ? x[rbase + (2 * p) * HW + g2] : 0.f;
                    float x1 = v2 ? x[rbase + (2 * p + 1) * HW + g2] : 0.f;
                    uint32_t x2;
                    asm("cvt.rn.f16x2.f32 %0, %1, %2;" : "=r"(x2) : "f"(x1), "f"(x0));
                    *(uint32_t*)(smb + SO_XROW + (p * 260 + 256 + tid) * 4) = x2;
                }
            }
        } else {
#pragma unroll 4
            for (int p = 0; p < 32; p++)
                *(uint32_t*)(smb + SO_XROW + (p * 260 + tid) * 4) = 0u;
            if (tid < 2)
                for (int p = 0; p < 32; p++)
                    *(uint32_t*)(smb + SO_XROW + (p * 260 + 256 + tid) * 4) = 0u;
        }
        __syncthreads();   // xrow visible

        for (int j = 0; j < 3; j++, slice++) {
            float awk = aw[slice], amk = am[slice];
            unsigned char* vbuf = smb + SO_V + (slice & 1) * 32768;

            // build V row for this pixel (warp-private region)
#pragma unroll
            for (int cb = 0; cb < 8; cb++) {
                uint32_t vp[4];
#pragma unroll
                for (int q = 0; q < 4; q++) {
                    int p = cb * 4 + q;
                    float e0 = wcoef[(2 * p) * 256 + tid];
                    float e1 = wcoef[(2 * p + 1) * 256 + tid];
                    float c0 = fmaf(amk, e0, awk);
                    float c1 = fmaf(amk, e1, awk);
                    uint32_t ch2;
                    asm("cvt.rn.f16x2.f32 %0, %1, %2;" : "=r"(ch2) : "f"(c1), "f"(c0));
                    uint32_t x2 = *(uint32_t*)(smb + SO_XROW + (p * 260 + tid + j) * 4);
                    asm("mul.rn.f16x2 %0, %1, %2;" : "=r"(vp[q]) : "r"(ch2), "r"(x2));
                }
                *(uint4*)(vbuf + SW128((uint32_t)(tid * 128 + cb * 16))) = *(uint4*)vp;
            }
            __syncwarp();   // warp's V rows visible to its ldmatrix

            uint32_t vb = sb + SO_V + (uint32_t)((slice & 1) * 32768 + wbase * 128);
            uint4 AH[2][4], AL[2][4];
#pragma unroll
            for (int mt = 0; mt < 4; mt++) {
                int fb = (slice * 16 + mt) * 2;
                AH[0][mt] = WF[(fb + 0) * 32 + lid];
                AL[0][mt] = WF[(fb + 1) * 32 + lid];
            }
#pragma unroll
            for (int ks = 0; ks < 4; ks++) {
                int cur = ks & 1;
                if (ks < 3) {
#pragma unroll
                    for (int mt = 0; mt < 4; mt++) {
                        int fb = (slice * 16 + (ks + 1) * 4 + mt) * 2;
                        AH[cur ^ 1][mt] = WF[(fb + 0) * 32 + lid];
                        AL[cur ^ 1][mt] = WF[(fb + 1) * 32 + lid];
                    }
                }
                uint32_t Bv[4][2];
#pragma unroll
                for (int nt = 0; nt < 4; nt++)
                    ldsm_x2(vb + nt * 1024 + bswz[ks], Bv[nt]);
#pragma unroll
                for (int mt = 0; mt < 4; mt++)
#pragma unroll
                    for (int nt = 0; nt < 4; nt++) {
                        mma16816(acc[mt][nt], (const uint32_t*)&AH[cur][mt], Bv[nt]);
                        mma16816(acc[mt][nt], (const uint32_t*)&AL[cur][mt], Bv[nt]);
                    }
            }
        }
    }

    // ---------- epilogue: unscale + stores + per-channel sums ----------
    float s8[8], q8[8];
#pragma unroll
    for (int i = 0; i < 8; i++) { s8[i] = 0.f; q8[i] = 0.f; }

    const int orow = lid >> 2;
    const int pixq = (lid & 3) * 2;
    const float inv64 = 0.015625f;
#pragma unroll
    for (int mt = 0; mt < 4; mt++) {
#pragma unroll
        for (int nt = 0; nt < 4; nt++) {
            float* c = acc[mt][nt];
            float c0 = c[0] * inv64, c1 = c[1] * inv64;
            float c2 = c[2] * inv64, c3 = c[3] * inv64;
            int o0 = mt * 16 + orow;
            int pix = wbase + nt * 8 + pixq;
            int g0 = ((b * COUTC + o0) * HIMG + y) * WIMG + col0 + pix;
            *(float2*)&out[g0] = make_float2(c0, c1);
            *(float2*)&out[g0 + 8 * HW] = make_float2(c2, c3);
            s8[mt * 2]     += c0 + c1;
            q8[mt * 2]     += c0 * c0 + c1 * c1;
            s8[mt * 2 + 1] += c2 + c3;
            q8[mt * 2 + 1] += c2 * c2 + c3 * c3;
        }
    }
#pragma unroll
    for (int i = 0; i < 8; i++) {
#pragma unroll
        for (int off = 1; off < 4; off <<= 1) {
            s8[i] += __shfl_xor_sync(0xffffffffu, s8[i], off);
            q8[i] += __shfl_xor_sync(0xffffffffu, q8[i], off);
        }
    }
    if ((lid & 3) == 0) {
#pragma unroll
        for (int i = 0; i < 8; i++) {
            int o = (i >> 1) * 16 + (i & 1) * 8 + orow;
            psum[wid * 64 + o] = s8[i];
            psq[wid * 64 + o] = q8[i];
        }
    }
    __syncthreads();
    if (tid < 64) {
        double a = 0.0;
        for (int w = 0; w < 8; w++) a += (double)psum[w * 64 + tid];
        atomicAdd(&g_sum[tid], a);
    } else if (tid < 128) {
        int c = tid - 64;
        double a = 0.0;
        for (int w = 0; w < 8; w++) a += (double)psq[w * 64 + c];
        atomicAdd(&g_sumsq[c], a);
    }
}

__global__ void bn_prep(const float* __restrict__ gamma, const float* __restrict__ beta) {
    int o = threadIdx.x;
    if (o < COUTC) {
        double n = 262144.0;
        double mu = g_sum[o] / n;
        double var = g_sumsq[o] / n - mu * mu;
        float rstd = rsqrtf((float)var + 1e-5f);
        float g = gamma[o] * rstd;
        g_scale[o] = g;
        g_bias[o] = fmaf(-(float)mu, g, beta[o]);
    }
}

__global__ void bn_kernel(float* __restrict__ out) {
    int idx = (blockIdx.x * blockDim.x + threadIdx.x) * 4;
    int o = (idx >> 17) & 63;
    float g = g_scale[o];
    float bb = g_bias[o];
    float4 v = *(float4*)&out[idx];
    v.x = fmaxf(fmaf(v.x, g, bb), 0.f);
    v.y = fmaxf(fmaf(v.y, g, bb), 0.f);
    v.z = fmaxf(fmaf(v.z, g, bb), 0.f);
    v.w = fmaxf(fmaf(v.w, g, bb), 0.f);
    *(float4*)&out[idx] = v;
}

extern "C" void kernel_launch(void* const* d_in, const int* in_sizes, int n_in,
                              void* d_out, int out_size) {
    const float* x         = (const float*)d_in[0];
    const int*   mask      = (const int*)d_in[1];
    const float* w_spatial = (const float*)d_in[2];
    const float* b_spatial = (const float*)d_in[3];
    const float* w_channel = (const float*)d_in[4];
    const float* b_channel = (const float*)d_in[5];
    const float* w_agg     = (const float*)d_in[6];
    const float* gamma     = (const float*)d_in[7];
    const float* beta      = (const float*)d_in[8];
    float* out = (float*)d_out;

    cudaFuncSetAttribute(main_kernel, cudaFuncAttributeMaxDynamicSharedMemorySize, SMEM_TOT);

    zero_kernel<<<1, 64>>>();
    wagg_prep<<<18, 256>>>(w_agg);
    dim3 grid(WIMG / TILE, HIMG, 2);
    main_kernel<<<grid, NTHREADS, SMEM_TOT>>>(x, mask, w_spatial, b_spatial,
                                              w_channel, b_channel, out);
    bn_prep<<<1, 64>>>(gamma, beta);
    int total4 = (2 * COUTC * HW) / 4;
    bn_kernel<<<total4 / 256, 256>>>(out);
}

// round 11
// speedup vs baseline: 1.0059x; 1.0059x over previous
#include <cuda_runtime.h>
#include <cuda_fp16.h>
#include <stdint.h>

#define WIMG 2048
#define HIMG 64
#define CINC 64
#define COUTC 64
#define TILE 256
#define NTHREADS 256
#define HW (HIMG*WIMG)

__device__ double g_sum[COUTC];
__device__ double g_sumsq[COUTC];
__device__ float  g_scale[COUTC];
__device__ float  g_bias[COUTC];
// A operand in mma.m16n8k16 fragment order: [slice][ks][mt][hi/lo][lane][4xu32], x64-scaled fp16
__device__ __align__(16) unsigned char g_wfrag[9 * 4 * 4 * 2 * 512];

#define SO_WSP    0
#define SO_BSP    1024
#define SO_WCH    1280
#define SO_BCH    2304
#define SO_PSUM   2560     /* 8 warps x 64 floats */
#define SO_PSQ    4608
#define SO_XROW   6656     /* 32 pairs x 260 half2 = 33280 */
#define SO_WCOEF  40960    /* 64*256*4 = 65536 */
#define SO_V      106496   /* 2 x 32768 (double-buffered fp16 V panel) */
#define SMEM_TOT  (172032 + 1024)

#define SW128(o) ((o) ^ (((o) >> 3) & 0x70))

__device__ __forceinline__ uint32_t smem_u32(const void* p) {
    uint32_t a;
    asm("{ .reg .u64 t; cvta.to.shared.u64 t, %1; cvt.u32.u64 %0, t; }" : "=r"(a) : "l"(p));
    return a;
}
__device__ __forceinline__ void ldsm_x2(uint32_t a, uint32_t* r) {
    asm volatile("ldmatrix.sync.aligned.m8n8.x2.shared.b16 {%0,%1}, [%2];"
                 : "=r"(r[0]), "=r"(r[1]) : "r"(a));
}
__device__ __forceinline__ void mma16816(float* c, const uint32_t* a, const uint32_t* b) {
    asm volatile("mma.sync.aligned.m16n8k16.row.col.f32.f16.f16.f32 "
                 "{%0,%1,%2,%3}, {%4,%5,%6,%7}, {%8,%9}, {%0,%1,%2,%3};"
                 : "+f"(c[0]), "+f"(c[1]), "+f"(c[2]), "+f"(c[3])
                 : "r"(a[0]), "r"(a[1]), "r"(a[2]), "r"(a[3]), "r"(b[0]), "r"(b[1]));
}

__global__ void zero_kernel() {
    int t = threadIdx.x;
    if (t < COUTC) { g_sum[t] = 0.0; g_sumsq[t] = 0.0; }
}

// write 64*w_agg as fp16 hi/lo in mma fragment layout
__global__ void wagg_prep(const float* __restrict__ w_agg) {
    int t = blockIdx.x * blockDim.x + threadIdx.x;
    if (t >= 9 * 4 * 4 * 32) return;
    int slice = t >> 9;
    int ks = (t >> 7) & 3;
    int mt = (t >> 5) & 3;
    int lane = t & 31;
    uint32_t hi[4], lo[4];
#pragma unroll
    for (int q = 0; q < 4; q++) {
        int row = mt * 16 + (lane >> 2) + (q & 1) * 8;
        int kc = ks * 16 + (lane & 3) * 2 + (q >> 1) * 8;
        float w0 = w_agg[row * 576 + slice * 64 + kc] * 64.0f;
        float w1 = w_agg[row * 576 + slice * 64 + kc + 1] * 64.0f;
        __half h0 = __float2half_rn(w0);
        __half h1 = __float2half_rn(w1);
        __half l0 = __float2half_rn(w0 - __half2float(h0));
        __half l1 = __float2half_rn(w1 - __half2float(h1));
        hi[q] = (uint32_t)__half_as_ushort(h0) | ((uint32_t)__half_as_ushort(h1) << 16);
        lo[q] = (uint32_t)__half_as_ushort(l0) | ((uint32_t)__half_as_ushort(l1) << 16);
    }
    int base = (slice * 16 + ks * 4 + mt) * 2;
    *(uint4*)(g_wfrag + (base + 0) * 512 + lane * 16) = *(uint4*)hi;
    *(uint4*)(g_wfrag + (base + 1) * 512 + lane * 16) = *(uint4*)lo;
}

__global__ void __launch_bounds__(NTHREADS, 1)
main_kernel(const float* __restrict__ x, const int* __restrict__ mask,
            const float* __restrict__ w_spatial, const float* __restrict__ b_spatial,
            const float* __restrict__ w_channel, const float* __restrict__ b_channel,
            float* __restrict__ out) {
    extern __shared__ unsigned char smraw[];
    const uint32_t raw = smem_u32(smraw);
    const uint32_t sb = (raw + 1023u) & ~1023u;
    unsigned char* smb = smraw + (sb - raw);

    float* wsp   = (float*)(smb + SO_WSP);
    float* bsp   = (float*)(smb + SO_BSP);
    float* wch   = (float*)(smb + SO_WCH);
    float* bch   = (float*)(smb + SO_BCH);
    float* psum  = (float*)(smb + SO_PSUM);
    float* psq   = (float*)(smb + SO_PSQ);
    float* wcoef = (float*)(smb + SO_WCOEF);

    const int tid = threadIdx.x;
    const int wid = tid >> 5;
    const int lid = tid & 31;
    const int col0 = blockIdx.x * TILE;
    const int y = blockIdx.y;
    const int b = blockIdx.z;

    for (int i = tid; i < CINC * 4; i += NTHREADS) { wsp[i] = w_spatial[i]; wch[i] = w_channel[i]; }
    for (int i = tid; i < CINC; i += NTHREADS) { bsp[i] = b_spatial[i]; bch[i] = b_channel[i]; }

    // ---------- phase A: dual-softmax prep (1 thread = 1 pixel) ----------
    const int col = col0 + tid;
    float d0[9], d1[9], d2[9], d3[9], mv[9];
    {
        int cbase = ((b * 67) * HIMG + y) * WIMG + col;
        float cc0 = x[cbase];
        float cc1 = x[cbase + HW];
        float cc2 = x[cbase + 2 * HW];
        float rc = sqrtf(cc0 * cc0 + cc1 * cc1 + cc2 * cc2);
#pragma unroll
        for (int k = 0; k < 9; k++) {
            int yy = y + k / 3 - 1;
            int xx = col + k % 3 - 1;
            bool v = (yy >= 0 && yy < HIMG && xx >= 0 && xx < WIMG);
            float p0 = 0.f, p1 = 0.f, p2 = 0.f, m = 0.f;
            if (v) {
                int base = ((b * 67) * HIMG + yy) * WIMG + xx;
                p0 = x[base]; p1 = x[base + HW]; p2 = x[base + 2 * HW];
                m = (float)mask[(b * HIMG + yy) * WIMG + xx];
            }
            float r = sqrtf(p0 * p0 + p1 * p1 + p2 * p2);
            d0[k] = p0 - cc0; d1[k] = p1 - cc1; d2[k] = p2 - cc2; d3[k] = r - rc;
            mv[k] = m;
        }
    }
    __syncthreads();   // weight copies visible

    float smax[9];
#pragma unroll
    for (int k = 0; k < 9; k++) smax[k] = -3.0e38f;
    float cmax = -3.0e38f;
    for (int c = 0; c < CINC; c++) {
        float ws0 = wsp[c*4], ws1 = wsp[c*4+1], ws2 = wsp[c*4+2], ws3 = wsp[c*4+3];
        float wc0 = wch[c*4], wc1 = wch[c*4+1], wc2 = wch[c*4+2], wc3 = wch[c*4+3];
        float bs = bsp[c], bc = bch[c];
        float tmax = -3.0e38f;
#pragma unroll
        for (int k = 0; k < 9; k++) {
            float sv = fmaf(d3[k], ws3, fmaf(d2[k], ws2, fmaf(d1[k], ws1, fmaf(d0[k], ws0, bs))));
            smax[k] = fmaxf(smax[k], sv);
            float tv = fmaf(d3[k], wc3, fmaf(d2[k], wc2, fmaf(d1[k], wc1, fmaf(d0[k], wc0, bc))));
            tmax = fmaxf(tmax, tv);
        }
        wcoef[c * 256 + tid] = tmax;   // thread-private column
        cmax = fmaxf(cmax, tmax);
    }
    float csum = 0.f;
    for (int c = 0; c < CINC; c++) {
        float e = __expf(wcoef[c * 256 + tid] - cmax);
        wcoef[c * 256 + tid] = e;
        csum += e;
    }
    float cinv = 1.f / csum;
    float wmx = smax[0];
#pragma unroll
    for (int k = 1; k < 9; k++) wmx = fmaxf(wmx, smax[k]);
    float es[9], ssum = 0.f;
#pragma unroll
    for (int k = 0; k < 9; k++) { es[k] = __expf(smax[k] - wmx); ssum += es[k]; }
    float sinv = 1.f / ssum;
    float aw[9], am[9];
#pragma unroll
    for (int k = 0; k < 9; k++) { aw[k] = mv[k] * es[k] * sinv; am[k] = mv[k] * cinv; }

    // ---------- phase B: fp16 2-product MMA, warp-desynchronized ----------
    const int wbase = wid * 32;
    uint32_t bswz[4];
    {
        uint32_t blocal = (uint32_t)((lid & 7) * 128 + ((lid >> 3) & 1) * 16);
#pragma unroll
        for (int ks = 0; ks < 4; ks++) bswz[ks] = SW128(blocal + ks * 32);
    }
    const uint4* WF = (const uint4*)g_wfrag;

    float acc[4][4][4];
#pragma unroll
    for (int mt = 0; mt < 4; mt++)
#pragma unroll
        for (int nt = 0; nt < 4; nt++)
#pragma unroll
            for (int q = 0; q < 4; q++) acc[mt][nt][q] = 0.f;

    int slice = 0;
    for (int i3 = 0; i3 < 3; i3++) {
        int yy = y + i3 - 1;
        __syncthreads();   // all readers of previous xrow done
        if (yy >= 0 && yy < HIMG) {
            int rbase = ((b * 67 + 3) * HIMG + yy) * WIMG;
            int gcol = col0 - 1 + tid;
            bool gv = (gcol >= 0 && gcol < WIMG);
#pragma unroll 4
            for (int p = 0; p < 32; p++) {
                float x0 = gv ? x[rbase + (2 * p) * HW + gcol] : 0.f;
                float x1 = gv ? x[rbase + (2 * p + 1) * HW + gcol] : 0.f;
                uint32_t x2;
                asm("cvt.rn.f16x2.f32 %0, %1, %2;" : "=r"(x2) : "f"(x1), "f"(x0));
                *(uint32_t*)(smb + SO_XROW + (p * 260 + tid) * 4) = x2;
            }
            if (tid < 2) {
                int g2 = col0 + 255 + tid;
                bool v2 = (g2 < WIMG);
                for (int p = 0; p < 32; p++) {
                    float x0 = v2 ? x[rbase + (2 * p) * HW + g2] : 0.f;
                    float x1 = v2 ? x[rbase + (2 * p + 1) * HW + g2] : 0.f;
                    uint32_t x2;
                    asm("cvt.rn.f16x2.f32 %0, %1, %2;" : "=r"(x2) : "f"(x1), "f"(x0));
                    *(uint32_t*)(smb + SO_XROW + (p * 260 + 256 + tid) * 4) = x2;
                }
            }
        } else {
#pragma unroll 4
            for (int p = 0; p < 32; p++)
                *(uint32_t*)(smb + SO_XROW + (p * 260 + tid) * 4) = 0u;
            if (tid < 2)
                for (int p = 0; p < 32; p++)
                    *(uint32_t*)(smb + SO_XROW + (p * 260 + 256 + tid) * 4) = 0u;
        }
        __syncthreads();   // xrow visible

        for (int j = 0; j < 3; j++, slice++) {
            float awk = aw[slice], amk = am[slice];
            unsigned char* vbuf = smb + SO_V + (slice & 1) * 32768;

            // build V row for this pixel (warp-private region)
#pragma unroll
            for (int cb = 0; cb < 8; cb++) {
                uint32_t vp[4];
#pragma unroll
                for (int q = 0; q < 4; q++) {
                    int p = cb * 4 + q;
                    float e0 = wcoef[(2 * p) * 256 + tid];
                    float e1 = wcoef[(2 * p + 1) * 256 + tid];
                    float c0 = fmaf(amk, e0, awk);
                    float c1 = fmaf(amk, e1, awk);
                    uint32_t ch2;
                    asm("cvt.rn.f16x2.f32 %0, %1, %2;" : "=r"(ch2) : "f"(c1), "f"(c0));
                    uint32_t x2 = *(uint32_t*)(smb + SO_XROW + (p * 260 + tid + j) * 4);
                    asm("mul.rn.f16x2 %0, %1, %2;" : "=r"(vp[q]) : "r"(ch2), "r"(x2));
                }
                *(uint4*)(vbuf + SW128((uint32_t)(tid * 128 + cb * 16))) = *(uint4*)vp;
            }
            __syncwarp();   // warp's V rows visible to its ldmatrix

            uint32_t vb = sb + SO_V + (uint32_t)((slice & 1) * 32768 + wbase * 128);
            uint4 AH[2][4], AL[2][4];
#pragma unroll
            for (int mt = 0; mt < 4; mt++) {
                int fb = (slice * 16 + mt) * 2;
                AH[0][mt] = WF[(fb + 0) * 32 + lid];
                AL[0][mt] = WF[(fb + 1) * 32 + lid];
            }
#pragma unroll
            for (int ks = 0; ks < 4; ks++) {
                int cur = ks & 1;
                if (ks < 3) {
#pragma unroll
                    for (int mt = 0; mt < 4; mt++) {
                        int fb = (slice * 16 + (ks + 1) * 4 + mt) * 2;
                        AH[cur ^ 1][mt] = WF[(fb + 0) * 32 + lid];
                        AL[cur ^ 1][mt] = WF[(fb + 1) * 32 + lid];
                    }
                }
                uint32_t Bv[4][2];
#pragma unroll
                for (int nt = 0; nt < 4; nt++)
                    ldsm_x2(vb + nt * 1024 + bswz[ks], Bv[nt]);
#pragma unroll
                for (int mt = 0; mt < 4; mt++)
#pragma unroll
                    for (int nt = 0; nt < 4; nt++) {
                        mma16816(acc[mt][nt], (const uint32_t*)&AH[cur][mt], Bv[nt]);
                        mma16816(acc[mt][nt], (const uint32_t*)&AL[cur][mt], Bv[nt]);
                    }
            }
        }
    }

    // ---------- epilogue: unscale + stores + per-channel sums ----------
    float s8[8], q8[8];
#pragma unroll
    for (int i = 0; i < 8; i++) { s8[i] = 0.f; q8[i] = 0.f; }

    const int orow = lid >> 2;
    const int pixq = (lid & 3) * 2;
    const float inv64 = 0.015625f;
#pragma unroll
    for (int mt = 0; mt < 4; mt++) {
#pragma unroll
        for (int nt = 0; nt < 4; nt++) {
            float* c = acc[mt][nt];
            float c0 = c[0] * inv64, c1 = c[1] * inv64;
            float c2 = c[2] * inv64, c3 = c[3] * inv64;
            int o0 = mt * 16 + orow;
            int pix = wbase + nt * 8 + pixq;
            int g0 = ((b * COUTC + o0) * HIMG + y) * WIMG + col0 + pix;
            *(float2*)&out[g0] = make_float2(c0, c1);
            *(float2*)&out[g0 + 8 * HW] = make_float2(c2, c3);
            s8[mt * 2]     += c0 + c1;
            q8[mt * 2]     += c0 * c0 + c1 * c1;
            s8[mt * 2 + 1] += c2 + c3;
            q8[mt * 2 + 1] += c2 * c2 + c3 * c3;
        }
    }
#pragma unroll
    for (int i = 0; i < 8; i++) {
#pragma unroll
        for (int off = 1; off < 4; off <<= 1) {
            s8[i] += __shfl_xor_sync(0xffffffffu, s8[i], off);
            q8[i] += __shfl_xor_sync(0xffffffffu, q8[i], off);
        }
    }
    if ((lid & 3) == 0) {
#pragma unroll
        for (int i = 0; i < 8; i++) {
            int o = (i >> 1) * 16 + (i & 1) * 8 + orow;
            psum[wid * 64 + o] = s8[i];
            psq[wid * 64 + o] = q8[i];
        }
    }
    __syncthreads();
    if (tid < 64) {
        double a = 0.0;
        for (int w = 0; w < 8; w++) a += (double)psum[w * 64 + tid];
        atomicAdd(&g_sum[tid], a);
    } else if (tid < 128) {
        int c = tid - 64;
        double a = 0.0;
        for (int w = 0; w < 8; w++) a += (double)psq[w * 64 + c];
        atomicAdd(&g_sumsq[c], a);
    }
}

__global__ void bn_prep(const float* __restrict__ gamma, const float* __restrict__ beta) {
    int o = threadIdx.x;
    if (o < COUTC) {
        double n = 262144.0;
        double mu = g_sum[o] / n;
        double var = g_sumsq[o] / n - mu * mu;
        float rstd = rsqrtf((float)var + 1e-5f);
        float g = gamma[o] * rstd;
        g_scale[o] = g;
        g_bias[o] = fmaf(-(float)mu, g, beta[o]);
    }
}

__global__ void bn_kernel(float* __restrict__ out) {
    int idx = (blockIdx.x * blockDim.x + threadIdx.x) * 4;
    int o = (idx >> 17) & 63;
    float g = g_scale[o];
    float bb = g_bias[o];
    float4 v = *(float4*)&out[idx];
    v.x = fmaxf(fmaf(v.x, g, bb), 0.f);
    v.y = fmaxf(fmaf(v.y, g, bb), 0.f);
    v.z = fmaxf(fmaf(v.z, g, bb), 0.f);
    v.w = fmaxf(fmaf(v.w, g, bb), 0.f);
    *(float4*)&out[idx] = v;
}

extern "C" void kernel_launch(void* const* d_in, const int* in_sizes, int n_in,
                              void* d_out, int out_size) {
    const float* x         = (const float*)d_in[0];
    const int*   mask      = (const int*)d_in[1];
    const float* w_spatial = (const float*)d_in[2];
    const float* b_spatial = (const float*)d_in[3];
    const float* w_channel = (const float*)d_in[4];
    const float* b_channel = (const float*)d_in[5];
    const float* w_agg     = (const float*)d_in[6];
    const float* gamma     = (const float*)d_in[7];
    const float* beta      = (const float*)d_in[8];
    float* out = (float*)d_out;

    cudaFuncSetAttribute(main_kernel, cudaFuncAttributeMaxDynamicSharedMemorySize, SMEM_TOT);

    zero_kernel<<<1, 64>>>();
    wagg_prep<<<18, 256>>>(w_agg);
    dim3 grid(WIMG / TILE, HIMG, 2);
    main_kernel<<<grid, NTHREADS, SMEM_TOT>>>(x, mask, w_spatial, b_spatial,
                                              w_channel, b_channel, out);
    bn_prep<<<1, 64>>>(gamma, beta);
    int total4 = (2 * COUTC * HW) / 4;
    bn_kernel<<<total4 / 256, 256>>>(out);
}

// round 12
// speedup vs baseline: 1.0105x; 1.0045x over previous
#include <cuda_runtime.h>
#include <cuda_fp16.h>
#include <stdint.h>

#define WIMG 2048
#define HIMG 64
#define CINC 64
#define COUTC 64
#define TILE 256
#define NTHREADS 256
#define HW (HIMG*WIMG)

__device__ double g_sum[COUTC];
__device__ double g_sumsq[COUTC];
__device__ float  g_scale[COUTC];
__device__ float  g_bias[COUTC];
// A operand in mma.m16n8k16 fragment order: [slice][ks][mt][hi/lo][lane][4xu32], x64-scaled fp16
__device__ __align__(16) unsigned char g_wfrag[9 * 4 * 4 * 2 * 512];

#define SO_WSP    0
#define SO_BSP    1024
#define SO_WCH    1280
#define SO_BCH    2304
#define SO_PSUM   2560     /* 8 warps x 64 floats */
#define SO_PSQ    4608
#define SO_XROW   6656     /* 32 pairs x 260 half2 = 33280 */
#define SO_WCOEF  40960    /* 64*256*4 = 65536 */
#define SO_V      106496   /* 2 x 32768 (double-buffered fp16 V panel) */
#define SMEM_TOT  (172032 + 1024)

#define SW128(o) ((o) ^ (((o) >> 3) & 0x70))

__device__ __forceinline__ uint32_t smem_u32(const void* p) {
    uint32_t a;
    asm("{ .reg .u64 t; cvta.to.shared.u64 t, %1; cvt.u32.u64 %0, t; }" : "=r"(a) : "l"(p));
    return a;
}
__device__ __forceinline__ void ldsm_x2(uint32_t a, uint32_t* r) {
    asm volatile("ldmatrix.sync.aligned.m8n8.x2.shared.b16 {%0,%1}, [%2];"
                 : "=r"(r[0]), "=r"(r[1]) : "r"(a));
}
__device__ __forceinline__ void mma16816(float* c, const uint32_t* a, const uint32_t* b) {
    asm volatile("mma.sync.aligned.m16n8k16.row.col.f32.f16.f16.f32 "
                 "{%0,%1,%2,%3}, {%4,%5,%6,%7}, {%8,%9}, {%0,%1,%2,%3};"
                 : "+f"(c[0]), "+f"(c[1]), "+f"(c[2]), "+f"(c[3])
                 : "r"(a[0]), "r"(a[1]), "r"(a[2]), "r"(a[3]), "r"(b[0]), "r"(b[1]));
}

__global__ void zero_kernel() {
    int t = threadIdx.x;
    if (t < COUTC) { g_sum[t] = 0.0; g_sumsq[t] = 0.0; }
}

// write 64*w_agg as fp16 hi/lo in mma fragment layout
__global__ void wagg_prep(const float* __restrict__ w_agg) {
    int t = blockIdx.x * blockDim.x + threadIdx.x;
    if (t >= 9 * 4 * 4 * 32) return;
    int slice = t >> 9;
    int ks = (t >> 7) & 3;
    int mt = (t >> 5) & 3;
    int lane = t & 31;
    uint32_t hi[4], lo[4];
#pragma unroll
    for (int q = 0; q < 4; q++) {
        int row = mt * 16 + (lane >> 2) + (q & 1) * 8;
        int kc = ks * 16 + (lane & 3) * 2 + (q >> 1) * 8;
        float w0 = w_agg[row * 576 + slice * 64 + kc] * 64.0f;
        float w1 = w_agg[row * 576 + slice * 64 + kc + 1] * 64.0f;
        __half h0 = __float2half_rn(w0);
        __half h1 = __float2half_rn(w1);
        __half l0 = __float2half_rn(w0 - __half2float(h0));
        __half l1 = __float2half_rn(w1 - __half2float(h1));
        hi[q] = (uint32_t)__half_as_ushort(h0) | ((uint32_t)__half_as_ushort(h1) << 16);
        lo[q] = (uint32_t)__half_as_ushort(l0) | ((uint32_t)__half_as_ushort(l1) << 16);
    }
    int base = (slice * 16 + ks * 4 + mt) * 2;
    *(uint4*)(g_wfrag + (base + 0) * 512 + lane * 16) = *(uint4*)hi;
    *(uint4*)(g_wfrag + (base + 1) * 512 + lane * 16) = *(uint4*)lo;
}

__global__ void __launch_bounds__(NTHREADS, 1)
main_kernel(const float* __restrict__ x, const int* __restrict__ mask,
            const float* __restrict__ w_spatial, const float* __restrict__ b_spatial,
            const float* __restrict__ w_channel, const float* __restrict__ b_channel,
            float* __restrict__ out) {
    extern __shared__ unsigned char smraw[];
    const uint32_t raw = smem_u32(smraw);
    const uint32_t sb = (raw + 1023u) & ~1023u;
    unsigned char* smb = smraw + (sb - raw);

    float* wsp   = (float*)(smb + SO_WSP);
    float* bsp   = (float*)(smb + SO_BSP);
    float* wch   = (float*)(smb + SO_WCH);
    float* bch   = (float*)(smb + SO_BCH);
    float* psum  = (float*)(smb + SO_PSUM);
    float* psq   = (float*)(smb + SO_PSQ);
    float* wcoef = (float*)(smb + SO_WCOEF);

    const int tid = threadIdx.x;
    const int wid = tid >> 5;
    const int lid = tid & 31;
    const int col0 = blockIdx.x * TILE;
    const int y = blockIdx.y;
    const int b = blockIdx.z;

    for (int i = tid; i < CINC * 4; i += NTHREADS) { wsp[i] = w_spatial[i]; wch[i] = w_channel[i]; }
    for (int i = tid; i < CINC; i += NTHREADS) { bsp[i] = b_spatial[i]; bch[i] = b_channel[i]; }

    // ---------- phase A: dual-softmax prep (1 thread = 1 pixel) ----------
    const int col = col0 + tid;
    float d0[9], d1[9], d2[9], d3[9], mv[9];
    {
        int cbase = ((b * 67) * HIMG + y) * WIMG + col;
        float cc0 = x[cbase];
        float cc1 = x[cbase + HW];
        float cc2 = x[cbase + 2 * HW];
        float rc = sqrtf(cc0 * cc0 + cc1 * cc1 + cc2 * cc2);
#pragma unroll
        for (int k = 0; k < 9; k++) {
            int yy = y + k / 3 - 1;
            int xx = col + k % 3 - 1;
            bool v = (yy >= 0 && yy < HIMG && xx >= 0 && xx < WIMG);
            float p0 = 0.f, p1 = 0.f, p2 = 0.f, m = 0.f;
            if (v) {
                int base = ((b * 67) * HIMG + yy) * WIMG + xx;
                p0 = x[base]; p1 = x[base + HW]; p2 = x[base + 2 * HW];
                m = (float)mask[(b * HIMG + yy) * WIMG + xx];
            }
            float r = sqrtf(p0 * p0 + p1 * p1 + p2 * p2);
            d0[k] = p0 - cc0; d1[k] = p1 - cc1; d2[k] = p2 - cc2; d3[k] = r - rc;
            mv[k] = m;
        }
    }
    __syncthreads();   // weight copies visible

    float smax[9];
#pragma unroll
    for (int k = 0; k < 9; k++) smax[k] = -3.0e38f;
    float cmax = -3.0e38f;
    for (int c = 0; c < CINC; c++) {
        float ws0 = wsp[c*4], ws1 = wsp[c*4+1], ws2 = wsp[c*4+2], ws3 = wsp[c*4+3];
        float wc0 = wch[c*4], wc1 = wch[c*4+1], wc2 = wch[c*4+2], wc3 = wch[c*4+3];
        float bs = bsp[c], bc = bch[c];
        float tmax = -3.0e38f;
#pragma unroll
        for (int k = 0; k < 9; k++) {
            float sv = fmaf(d3[k], ws3, fmaf(d2[k], ws2, fmaf(d1[k], ws1, fmaf(d0[k], ws0, bs))));
            smax[k] = fmaxf(smax[k], sv);
            float tv = fmaf(d3[k], wc3, fmaf(d2[k], wc2, fmaf(d1[k], wc1, fmaf(d0[k], wc0, bc))));
            tmax = fmaxf(tmax, tv);
        }
        wcoef[c * 256 + tid] = tmax;   // thread-private column
        cmax = fmaxf(cmax, tmax);
    }
    float csum = 0.f;
    for (int c = 0; c < CINC; c++) {
        float e = __expf(wcoef[c * 256 + tid] - cmax);
        wcoef[c * 256 + tid] = e;
        csum += e;
    }
    float cinv = 1.f / csum;
    float wmx = smax[0];
#pragma unroll
    for (int k = 1; k < 9; k++) wmx = fmaxf(wmx, smax[k]);
    float es[9], ssum = 0.f;
#pragma unroll
    for (int k = 0; k < 9; k++) { es[k] = __expf(smax[k] - wmx); ssum += es[k]; }
    float sinv = 1.f / ssum;
    float aw[9], am[9];
#pragma unroll
    for (int k = 0; k < 9; k++) { aw[k] = mv[k] * es[k] * sinv; am[k] = mv[k] * cinv; }

    // ---------- phase B: fp16 2-product MMA, warp-desynchronized ----------
    const int wbase = wid * 32;
    uint32_t bswz[4];
    {
        uint32_t blocal = (uint32_t)((lid & 7) * 128 + ((lid >> 3) & 1) * 16);
#pragma unroll
        for (int ks = 0; ks < 4; ks++) bswz[ks] = SW128(blocal + ks * 32);
    }
    const uint4* WF = (const uint4*)g_wfrag;

    float acc[4][4][4];
#pragma unroll
    for (int mt = 0; mt < 4; mt++)
#pragma unroll
        for (int nt = 0; nt < 4; nt++)
#pragma unroll
            for (int q = 0; q < 4; q++) acc[mt][nt][q] = 0.f;

    int slice = 0;
    for (int i3 = 0; i3 < 3; i3++) {
        int yy = y + i3 - 1;
        __syncthreads();   // all readers of previous xrow done
        if (yy >= 0 && yy < HIMG) {
            int rbase = ((b * 67 + 3) * HIMG + yy) * WIMG;
            int gcol = col0 - 1 + tid;
            bool gv = (gcol >= 0 && gcol < WIMG);
#pragma unroll 4
            for (int p = 0; p < 32; p++) {
                float x0 = gv ? x[rbase + (2 * p) * HW + gcol] : 0.f;
                float x1 = gv ? x[rbase + (2 * p + 1) * HW + gcol] : 0.f;
                uint32_t x2;
                asm("cvt.rn.f16x2.f32 %0, %1, %2;" : "=r"(x2) : "f"(x1), "f"(x0));
                *(uint32_t*)(smb + SO_XROW + (p * 260 + tid) * 4) = x2;
            }
            if (tid < 2) {
                int g2 = col0 + 255 + tid;
                bool v2 = (g2 < WIMG);
                for (int p = 0; p < 32; p++) {
                    float x0 = v2 ? x[rbase + (2 * p) * HW + g2] : 0.f;
                    float x1 = v2 ? x[rbase + (2 * p + 1) * HW + g2] : 0.f;
                    uint32_t x2;
                    asm("cvt.rn.f16x2.f32 %0, %1, %2;" : "=r"(x2) : "f"(x1), "f"(x0));
                    *(uint32_t*)(smb + SO_XROW + (p * 260 + 256 + tid) * 4) = x2;
                }
            }
        } else {
#pragma unroll 4
            for (int p = 0; p < 32; p++)
                *(uint32_t*)(smb + SO_XROW + (p * 260 + tid) * 4) = 0u;
            if (tid < 2)
                for (int p = 0; p < 32; p++)
                    *(uint32_t*)(smb + SO_XROW + (p * 260 + 256 + tid) * 4) = 0u;
        }
        __syncthreads();   // xrow visible

        for (int j = 0; j < 3; j++, slice++) {
            float awk = aw[slice], amk = am[slice];
            unsigned char* vbuf = smb + SO_V + (slice & 1) * 32768;

            // build V row for this pixel (warp-private region)
#pragma unroll
            for (int cb = 0; cb < 8; cb++) {
                uint32_t vp[4];
#pragma unroll
                for (int q = 0; q < 4; q++) {
                    int p = cb * 4 + q;
                    float e0 = wcoef[(2 * p) * 256 + tid];
                    float e1 = wcoef[(2 * p + 1) * 256 + tid];
                    float c0 = fmaf(amk, e0, awk);
                    float c1 = fmaf(amk, e1, awk);
                    uint32_t ch2;
                    asm("cvt.rn.f16x2.f32 %0, %1, %2;" : "=r"(ch2) : "f"(c1), "f"(c0));
                    uint32_t x2 = *(uint32_t*)(smb + SO_XROW + (p * 260 + tid + j) * 4);
                    asm("mul.rn.f16x2 %0, %1, %2;" : "=r"(vp[q]) : "r"(ch2), "r"(x2));
                }
                *(uint4*)(vbuf + SW128((uint32_t)(tid * 128 + cb * 16))) = *(uint4*)vp;
            }
            __syncwarp();   // warp's V rows visible to its ldmatrix

            uint32_t vb = sb + SO_V + (uint32_t)((slice & 1) * 32768 + wbase * 128);
            uint4 AH[2][4], AL[2][4];
#pragma unroll
            for (int mt = 0; mt < 4; mt++) {
                int fb = (slice * 16 + mt) * 2;
                AH[0][mt] = WF[(fb + 0) * 32 + lid];
                AL[0][mt] = WF[(fb + 1) * 32 + lid];
            }
#pragma unroll
            for (int ks = 0; ks < 4; ks++) {
                int cur = ks & 1;
                if (ks < 3) {
#pragma unroll
                    for (int mt = 0; mt < 4; mt++) {
                        int fb = (slice * 16 + (ks + 1) * 4 + mt) * 2;
                        AH[cur ^ 1][mt] = WF[(fb + 0) * 32 + lid];
                        AL[cur ^ 1][mt] = WF[(fb + 1) * 32 + lid];
                    }
                }
                uint32_t Bv[4][2];
#pragma unroll
                for (int nt = 0; nt < 4; nt++)
                    ldsm_x2(vb + nt * 1024 + bswz[ks], Bv[nt]);
#pragma unroll
                for (int mt = 0; mt < 4; mt++)
#pragma unroll
                    for (int nt = 0; nt < 4; nt++) {
                        mma16816(acc[mt][nt], (const uint32_t*)&AH[cur][mt], Bv[nt]);
                        mma16816(acc[mt][nt], (const uint32_t*)&AL[cur][mt], Bv[nt]);
                    }
            }
        }
    }

    // ---------- epilogue: unscale + stores + per-channel sums ----------
    float s8[8], q8[8];
#pragma unroll
    for (int i = 0; i < 8; i++) { s8[i] = 0.f; q8[i] = 0.f; }

    const int orow = lid >> 2;
    const int pixq = (lid & 3) * 2;
    const float inv64 = 0.015625f;
#pragma unroll
    for (int mt = 0; mt < 4; mt++) {
#pragma unroll
        for (int nt = 0; nt < 4; nt++) {
            float* c = acc[mt][nt];
            float c0 = c[0] * inv64, c1 = c[1] * inv64;
            float c2 = c[2] * inv64, c3 = c[3] * inv64;
            int o0 = mt * 16 + orow;
            int pix = wbase + nt * 8 + pixq;
            int g0 = ((b * COUTC + o0) * HIMG + y) * WIMG + col0 + pix;
            *(float2*)&out[g0] = make_float2(c0, c1);
            *(float2*)&out[g0 + 8 * HW] = make_float2(c2, c3);
            s8[mt * 2]     += c0 + c1;
            q8[mt * 2]     += c0 * c0 + c1 * c1;
            s8[mt * 2 + 1] += c2 + c3;
            q8[mt * 2 + 1] += c2 * c2 + c3 * c3;
        }
    }
#pragma unroll
    for (int i = 0; i < 8; i++) {
#pragma unroll
        for (int off = 1; off < 4; off <<= 1) {
            s8[i] += __shfl_xor_sync(0xffffffffu, s8[i], off);
            q8[i] += __shfl_xor_sync(0xffffffffu, q8[i], off);
        }
    }
    if ((lid & 3) == 0) {
#pragma unroll
        for (int i = 0; i < 8; i++) {
            int o = (i >> 1) * 16 + (i & 1) * 8 + orow;
            psum[wid * 64 + o] = s8[i];
            psq[wid * 64 + o] = q8[i];
        }
    }
    __syncthreads();
    if (tid < 64) {
        double a = 0.0;
        for (int w = 0; w < 8; w++) a += (double)psum[w * 64 + tid];
        atomicAdd(&g_sum[tid], a);
    } else if (tid < 128) {
        int c = tid - 64;
        double a = 0.0;
        for (int w = 0; w < 8; w++) a += (double)psq[w * 64 + c];
        atomicAdd(&g_sumsq[c], a);
    }
}

__global__ void bn_prep(const float* __restrict__ gamma, const float* __restrict__ beta) {
    int o = threadIdx.x;
    if (o < COUTC) {
        double n = 262144.0;
        double mu = g_sum[o] / n;
        double var = g_sumsq[o] / n - mu * mu;
        float rstd = rsqrtf((float)var + 1e-5f);
        float g = gamma[o] * rstd;
        g_scale[o] = g;
        g_bias[o] = fmaf(-(float)mu, g, beta[o]);
    }
}

__global__ void bn_kernel(float* __restrict__ out) {
    int idx = (blockIdx.x * blockDim.x + threadIdx.x) * 4;
    int o = (idx >> 17) & 63;
    float g = g_scale[o];
    float bb = g_bias[o];
    float4 v = *(float4*)&out[idx];
    v.x = fmaxf(fmaf(v.x, g, bb), 0.f);
    v.y = fmaxf(fmaf(v.y, g, bb), 0.f);
    v.z = fmaxf(fmaf(v.z, g, bb), 0.f);
    v.w = fmaxf(fmaf(v.w, g, bb), 0.f);
    *(float4*)&out[idx] = v;
}

extern "C" void kernel_launch(void* const* d_in, const int* in_sizes, int n_in,
                              void* d_out, int out_size) {
    const float* x         = (const float*)d_in[0];
    const int*   mask      = (const int*)d_in[1];
    const float* w_spatial = (const float*)d_in[2];
    const float* b_spatial = (const float*)d_in[3];
    const float* w_channel = (const float*)d_in[4];
    const float* b_channel = (const float*)d_in[5];
    const float* w_agg     = (const float*)d_in[6];
    const float* gamma     = (const float*)d_in[7];
    const float* beta      = (const float*)d_in[8];
    float* out = (float*)d_out;

    cudaFuncSetAttribute(main_kernel, cudaFuncAttributeMaxDynamicSharedMemorySize, SMEM_TOT);

    zero_kernel<<<1, 64>>>();
    wagg_prep<<<18, 256>>>(w_agg);
    dim3 grid(WIMG / TILE, HIMG, 2);
    main_kernel<<<grid, NTHREADS, SMEM_TOT>>>(x, mask, w_spatial, b_spatial,
                                              w_channel, b_channel, out);
    bn_prep<<<1, 64>>>(gamma, beta);
    int total4 = (2 * COUTC * HW) / 4;
    bn_kernel<<<total4 / 256, 256>>>(out);
}

// round 13
// speedup vs baseline: 1.0116x; 1.0011x over previous
#include <cuda_runtime.h>
#include <cuda_fp16.h>
#include <stdint.h>

#define WIMG 2048
#define HIMG 64
#define CINC 64
#define COUTC 64
#define TILE 256
#define NTHREADS 256
#define HW (HIMG*WIMG)

__device__ double g_sum[COUTC];
__device__ double g_sumsq[COUTC];
__device__ float  g_scale[COUTC];
__device__ float  g_bias[COUTC];
// A operand in mma.m16n8k16 fragment order: [slice][ks][mt][hi/lo][lane][4xu32], x64-scaled fp16
__device__ __align__(16) unsigned char g_wfrag[9 * 4 * 4 * 2 * 512];

#define SO_WSP    0
#define SO_BSP    1024
#define SO_WCH    1280
#define SO_BCH    2304
#define SO_PSUM   2560     /* 8 warps x 64 floats */
#define SO_PSQ    4608
#define SO_XROW   6656     /* 32 pairs x 260 half2 = 33280 */
#define SO_WCOEF  40960    /* 64*256*4 = 65536 */
#define SO_V      106496   /* 2 x 32768 (double-buffered fp16 V panel) */
#define SMEM_TOT  (172032 + 1024)

#define SW128(o) ((o) ^ (((o) >> 3) & 0x70))

__device__ __forceinline__ uint32_t smem_u32(const void* p) {
    uint32_t a;
    asm("{ .reg .u64 t; cvta.to.shared.u64 t, %1; cvt.u32.u64 %0, t; }" : "=r"(a) : "l"(p));
    return a;
}
__device__ __forceinline__ void ldsm_x2(uint32_t a, uint32_t* r) {
    asm volatile("ldmatrix.sync.aligned.m8n8.x2.shared.b16 {%0,%1}, [%2];"
                 : "=r"(r[0]), "=r"(r[1]) : "r"(a));
}
__device__ __forceinline__ void mma16816(float* c, const uint32_t* a, const uint32_t* b) {
    asm volatile("mma.sync.aligned.m16n8k16.row.col.f32.f16.f16.f32 "
                 "{%0,%1,%2,%3}, {%4,%5,%6,%7}, {%8,%9}, {%0,%1,%2,%3};"
                 : "+f"(c[0]), "+f"(c[1]), "+f"(c[2]), "+f"(c[3])
                 : "r"(a[0]), "r"(a[1]), "r"(a[2]), "r"(a[3]), "r"(b[0]), "r"(b[1]));
}

__global__ void zero_kernel() {
    int t = threadIdx.x;
    if (t < COUTC) { g_sum[t] = 0.0; g_sumsq[t] = 0.0; }
}

// write 64*w_agg as fp16 hi/lo in mma fragment layout
__global__ void wagg_prep(const float* __restrict__ w_agg) {
    int t = blockIdx.x * blockDim.x + threadIdx.x;
    if (t >= 9 * 4 * 4 * 32) return;
    int slice = t >> 9;
    int ks = (t >> 7) & 3;
    int mt = (t >> 5) & 3;
    int lane = t & 31;
    uint32_t hi[4], lo[4];
#pragma unroll
    for (int q = 0; q < 4; q++) {
        int row = mt * 16 + (lane >> 2) + (q & 1) * 8;
        int kc = ks * 16 + (lane & 3) * 2 + (q >> 1) * 8;
        float w0 = w_agg[row * 576 + slice * 64 + kc] * 64.0f;
        float w1 = w_agg[row * 576 + slice * 64 + kc + 1] * 64.0f;
        __half h0 = __float2half_rn(w0);
        __half h1 = __float2half_rn(w1);
        __half l0 = __float2half_rn(w0 - __half2float(h0));
        __half l1 = __float2half_rn(w1 - __half2float(h1));
        hi[q] = (uint32_t)__half_as_ushort(h0) | ((uint32_t)__half_as_ushort(h1) << 16);
        lo[q] = (uint32_t)__half_as_ushort(l0) | ((uint32_t)__half_as_ushort(l1) << 16);
    }
    int base = (slice * 16 + ks * 4 + mt) * 2;
    *(uint4*)(g_wfrag + (base + 0) * 512 + lane * 16) = *(uint4*)hi;
    *(uint4*)(g_wfrag + (base + 1) * 512 + lane * 16) = *(uint4*)lo;
}

__global__ void __launch_bounds__(NTHREADS, 1)
main_kernel(const float* __restrict__ x, const int* __restrict__ mask,
            const float* __restrict__ w_spatial, const float* __restrict__ b_spatial,
            const float* __restrict__ w_channel, const float* __restrict__ b_channel,
            float* __restrict__ out) {
    extern __shared__ unsigned char smraw[];
    const uint32_t raw = smem_u32(smraw);
    const uint32_t sb = (raw + 1023u) & ~1023u;
    unsigned char* smb = smraw + (sb - raw);

    float* wsp   = (float*)(smb + SO_WSP);
    float* bsp   = (float*)(smb + SO_BSP);
    float* wch   = (float*)(smb + SO_WCH);
    float* bch   = (float*)(smb + SO_BCH);
    float* psum  = (float*)(smb + SO_PSUM);
    float* psq   = (float*)(smb + SO_PSQ);
    float* wcoef = (float*)(smb + SO_WCOEF);

    const int tid = threadIdx.x;
    const int wid = tid >> 5;
    const int lid = tid & 31;
    const int col0 = blockIdx.x * TILE;
    const int y = blockIdx.y;
    const int b = blockIdx.z;

    for (int i = tid; i < CINC * 4; i += NTHREADS) { wsp[i] = w_spatial[i]; wch[i] = w_channel[i]; }
    for (int i = tid; i < CINC; i += NTHREADS) { bsp[i] = b_spatial[i]; bch[i] = b_channel[i]; }

    // ---------- phase A: dual-softmax prep (1 thread = 1 pixel) ----------
    const int col = col0 + tid;
    float d0[9], d1[9], d2[9], d3[9], mv[9];
    {
        int cbase = ((b * 67) * HIMG + y) * WIMG + col;
        float cc0 = x[cbase];
        float cc1 = x[cbase + HW];
        float cc2 = x[cbase + 2 * HW];
        float rc = sqrtf(cc0 * cc0 + cc1 * cc1 + cc2 * cc2);
#pragma unroll
        for (int k = 0; k < 9; k++) {
            int yy = y + k / 3 - 1;
            int xx = col + k % 3 - 1;
            bool v = (yy >= 0 && yy < HIMG && xx >= 0 && xx < WIMG);
            float p0 = 0.f, p1 = 0.f, p2 = 0.f, m = 0.f;
            if (v) {
                int base = ((b * 67) * HIMG + yy) * WIMG + xx;
                p0 = x[base]; p1 = x[base + HW]; p2 = x[base + 2 * HW];
                m = (float)mask[(b * HIMG + yy) * WIMG + xx];
            }
            float r = sqrtf(p0 * p0 + p1 * p1 + p2 * p2);
            d0[k] = p0 - cc0; d1[k] = p1 - cc1; d2[k] = p2 - cc2; d3[k] = r - rc;
            mv[k] = m;
        }
    }
    __syncthreads();   // weight copies visible

    float smax[9];
#pragma unroll
    for (int k = 0; k < 9; k++) smax[k] = -3.0e38f;
    float cmax = -3.0e38f;
    for (int c = 0; c < CINC; c++) {
        float ws0 = wsp[c*4], ws1 = wsp[c*4+1], ws2 = wsp[c*4+2], ws3 = wsp[c*4+3];
        float wc0 = wch[c*4], wc1 = wch[c*4+1], wc2 = wch[c*4+2], wc3 = wch[c*4+3];
        float bs = bsp[c], bc = bch[c];
        float tmax = -3.0e38f;
#pragma unroll
        for (int k = 0; k < 9; k++) {
            float sv = fmaf(d3[k], ws3, fmaf(d2[k], ws2, fmaf(d1[k], ws1, fmaf(d0[k], ws0, bs))));
            smax[k] = fmaxf(smax[k], sv);
            float tv = fmaf(d3[k], wc3, fmaf(d2[k], wc2, fmaf(d1[k], wc1, fmaf(d0[k], wc0, bc))));
            tmax = fmaxf(tmax, tv);
        }
        wcoef[c * 256 + tid] = tmax;   // thread-private column
        cmax = fmaxf(cmax, tmax);
    }
    float csum = 0.f;
    for (int c = 0; c < CINC; c++) {
        float e = __expf(wcoef[c * 256 + tid] - cmax);
        wcoef[c * 256 + tid] = e;
        csum += e;
    }
    float cinv = 1.f / csum;
    float wmx = smax[0];
#pragma unroll
    for (int k = 1; k < 9; k++) wmx = fmaxf(wmx, smax[k]);
    float es[9], ssum = 0.f;
#pragma unroll
    for (int k = 0; k < 9; k++) { es[k] = __expf(smax[k] - wmx); ssum += es[k]; }
    float sinv = 1.f / ssum;
    float aw[9], am[9];
#pragma unroll
    for (int k = 0; k < 9; k++) { aw[k] = mv[k] * es[k] * sinv; am[k] = mv[k] * cinv; }

    // ---------- phase B: fp16 2-product MMA, warp-desynchronized ----------
    const int wbase = wid * 32;
    uint32_t bswz[4];
    {
        uint32_t blocal = (uint32_t)((lid & 7) * 128 + ((lid >> 3) & 1) * 16);
#pragma unroll
        for (int ks = 0; ks < 4; ks++) bswz[ks] = SW128(blocal + ks * 32);
    }
    const uint4* WF = (const uint4*)g_wfrag;

    float acc[4][4][4];
#pragma unroll
    for (int mt = 0; mt < 4; mt++)
#pragma unroll
        for (int nt = 0; nt < 4; nt++)
#pragma unroll
            for (int q = 0; q < 4; q++) acc[mt][nt][q] = 0.f;

    int slice = 0;
    for (int i3 = 0; i3 < 3; i3++) {
        int yy = y + i3 - 1;
        __syncthreads();   // all readers of previous xrow done
        if (yy >= 0 && yy < HIMG) {
            int rbase = ((b * 67 + 3) * HIMG + yy) * WIMG;
            int gcol = col0 - 1 + tid;
            bool gv = (gcol >= 0 && gcol < WIMG);
#pragma unroll 4
            for (int p = 0; p < 32; p++) {
                float x0 = gv ? x[rbase + (2 * p) * HW + gcol] : 0.f;
                float x1 = gv ? x[rbase + (2 * p + 1) * HW + gcol] : 0.f;
                uint32_t x2;
                asm("cvt.rn.f16x2.f32 %0, %1, %2;" : "=r"(x2) : "f"(x1), "f"(x0));
                *(uint32_t*)(smb + SO_XROW + (p * 260 + tid) * 4) = x2;
            }
            if (tid < 2) {
                int g2 = col0 + 255 + tid;
                bool v2 = (g2 < WIMG);
                for (int p = 0; p < 32; p++) {
                    float x0 = v2 ? x[rbase + (2 * p) * HW + g2] : 0.f;
                    float x1 = v2 ? x[rbase + (2 * p + 1) * HW + g2] : 0.f;
                    uint32_t x2;
                    asm("cvt.rn.f16x2.f32 %0, %1, %2;" : "=r"(x2) : "f"(x1), "f"(x0));
                    *(uint32_t*)(smb + SO_XROW + (p * 260 + 256 + tid) * 4) = x2;
                }
            }
        } else {
#pragma unroll 4
            for (int p = 0; p < 32; p++)
                *(uint32_t*)(smb + SO_XROW + (p * 260 + tid) * 4) = 0u;
            if (tid < 2)
                for (int p = 0; p < 32; p++)
                    *(uint32_t*)(smb + SO_XROW + (p * 260 + 256 + tid) * 4) = 0u;
        }
        __syncthreads();   // xrow visible

        for (int j = 0; j < 3; j++, slice++) {
            float awk = aw[slice], amk = am[slice];
            unsigned char* vbuf = smb + SO_V + (slice & 1) * 32768;

            // build V row for this pixel (warp-private region)
#pragma unroll
            for (int cb = 0; cb < 8; cb++) {
                uint32_t vp[4];
#pragma unroll
                for (int q = 0; q < 4; q++) {
                    int p = cb * 4 + q;
                    float e0 = wcoef[(2 * p) * 256 + tid];
                    float e1 = wcoef[(2 * p + 1) * 256 + tid];
                    float c0 = fmaf(amk, e0, awk);
                    float c1 = fmaf(amk, e1, awk);
                    uint32_t ch2;
                    asm("cvt.rn.f16x2.f32 %0, %1, %2;" : "=r"(ch2) : "f"(c1), "f"(c0));
                    uint32_t x2 = *(uint32_t*)(smb + SO_XROW + (p * 260 + tid + j) * 4);
                    asm("mul.rn.f16x2 %0, %1, %2;" : "=r"(vp[q]) : "r"(ch2), "r"(x2));
                }
                *(uint4*)(vbuf + SW128((uint32_t)(tid * 128 + cb * 16))) = *(uint4*)vp;
            }
            __syncwarp();   // warp's V rows visible to its ldmatrix

            uint32_t vb = sb + SO_V + (uint32_t)((slice & 1) * 32768 + wbase * 128);
            uint4 AH[2][4], AL[2][4];
#pragma unroll
            for (int mt = 0; mt < 4; mt++) {
                int fb = (slice * 16 + mt) * 2;
                AH[0][mt] = WF[(fb + 0) * 32 + lid];
                AL[0][mt] = WF[(fb + 1) * 32 + lid];
            }
#pragma unroll
            for (int ks = 0; ks < 4; ks++) {
                int cur = ks & 1;
                if (ks < 3) {
#pragma unroll
                    for (int mt = 0; mt < 4; mt++) {
                        int fb = (slice * 16 + (ks + 1) * 4 + mt) * 2;
                        AH[cur ^ 1][mt] = WF[(fb + 0) * 32 + lid];
                        AL[cur ^ 1][mt] = WF[(fb + 1) * 32 + lid];
                    }
                }
                uint32_t Bv[4][2];
#pragma unroll
                for (int nt = 0; nt < 4; nt++)
                    ldsm_x2(vb + nt * 1024 + bswz[ks], Bv[nt]);
#pragma unroll
                for (int mt = 0; mt < 4; mt++)
#pragma unroll
                    for (int nt = 0; nt < 4; nt++) {
                        mma16816(acc[mt][nt], (const uint32_t*)&AH[cur][mt], Bv[nt]);
                        mma16816(acc[mt][nt], (const uint32_t*)&AL[cur][mt], Bv[nt]);
                    }
            }
        }
    }

    // ---------- epilogue: unscale + stores + per-channel sums ----------
    float s8[8], q8[8];
#pragma unroll
    for (int i = 0; i < 8; i++) { s8[i] = 0.f; q8[i] = 0.f; }

    const int orow = lid >> 2;
    const int pixq = (lid & 3) * 2;
    const float inv64 = 0.015625f;
#pragma unroll
    for (int mt = 0; mt < 4; mt++) {
#pragma unroll
        for (int nt = 0; nt < 4; nt++) {
            float* c = acc[mt][nt];
            float c0 = c[0] * inv64, c1 = c[1] * inv64;
            float c2 = c[2] * inv64, c3 = c[3] * inv64;
            int o0 = mt * 16 + orow;
            int pix = wbase + nt * 8 + pixq;
            int g0 = ((b * COUTC + o0) * HIMG + y) * WIMG + col0 + pix;
            *(float2*)&out[g0] = make_float2(c0, c1);
            *(float2*)&out[g0 + 8 * HW] = make_float2(c2, c3);
            s8[mt * 2]     += c0 + c1;
            q8[mt * 2]     += c0 * c0 + c1 * c1;
            s8[mt * 2 + 1] += c2 + c3;
            q8[mt * 2 + 1] += c2 * c2 + c3 * c3;
        }
    }
#pragma unroll
    for (int i = 0; i < 8; i++) {
#pragma unroll
        for (int off = 1; off < 4; off <<= 1) {
            s8[i] += __shfl_xor_sync(0xffffffffu, s8[i], off);
            q8[i] += __shfl_xor_sync(0xffffffffu, q8[i], off);
        }
    }
    if ((lid & 3) == 0) {
#pragma unroll
        for (int i = 0; i < 8; i++) {
            int o = (i >> 1) * 16 + (i & 1) * 8 + orow;
            psum[wid * 64 + o] = s8[i];
            psq[wid * 64 + o] = q8[i];
        }
    }
    __syncthreads();
    if (tid < 64) {
        double a = 0.0;
        for (int w = 0; w < 8; w++) a += (double)psum[w * 64 + tid];
        atomicAdd(&g_sum[tid], a);
    } else if (tid < 128) {
        int c = tid - 64;
        double a = 0.0;
        for (int w = 0; w < 8; w++) a += (double)psq[w * 64 + c];
        atomicAdd(&g_sumsq[c], a);
    }
}

__global__ void bn_prep(const float* __restrict__ gamma, const float* __restrict__ beta) {
    int o = threadIdx.x;
    if (o < COUTC) {
        double n = 262144.0;
        double mu = g_sum[o] / n;
        double var = g_sumsq[o] / n - mu * mu;
        float rstd = rsqrtf((float)var + 1e-5f);
        float g = gamma[o] * rstd;
        g_scale[o] = g;
        g_bias[o] = fmaf(-(float)mu, g, beta[o]);
    }
}

__global__ void bn_kernel(float* __restrict__ out) {
    int idx = (blockIdx.x * blockDim.x + threadIdx.x) * 4;
    int o = (idx >> 17) & 63;
    float g = g_scale[o];
    float bb = g_bias[o];
    float4 v = *(float4*)&out[idx];
    v.x = fmaxf(fmaf(v.x, g, bb), 0.f);
    v.y = fmaxf(fmaf(v.y, g, bb), 0.f);
    v.z = fmaxf(fmaf(v.z, g, bb), 0.f);
    v.w = fmaxf(fmaf(v.w, g, bb), 0.f);
    *(float4*)&out[idx] = v;
}

extern "C" void kernel_launch(void* const* d_in, const int* in_sizes, int n_in,
                              void* d_out, int out_size) {
    const float* x         = (const float*)d_in[0];
    const int*   mask      = (const int*)d_in[1];
    const float* w_spatial = (const float*)d_in[2];
    const float* b_spatial = (const float*)d_in[3];
    const float* w_channel = (const float*)d_in[4];
    const float* b_channel = (const float*)d_in[5];
    const float* w_agg     = (const float*)d_in[6];
    const float* gamma     = (const float*)d_in[7];
    const float* beta      = (const float*)d_in[8];
    float* out = (float*)d_out;

    cudaFuncSetAttribute(main_kernel, cudaFuncAttributeMaxDynamicSharedMemorySize, SMEM_TOT);

    zero_kernel<<<1, 64>>>();
    wagg_prep<<<18, 256>>>(w_agg);
    dim3 grid(WIMG / TILE, HIMG, 2);
    main_kernel<<<grid, NTHREADS, SMEM_TOT>>>(x, mask, w_spatial, b_spatial,
                                              w_channel, b_channel, out);
    bn_prep<<<1, 64>>>(gamma, beta);
    int total4 = (2 * COUTC * HW) / 4;
    bn_kernel<<<total4 / 256, 256>>>(out);
}